// round 17
// baseline (speedup 1.0000x reference)
#include <cuda_runtime.h>
#include <cuda_fp16.h>
#include <cstdint>

// ---------------------------------------------------------------------------
// KAN 3-layer (12->64->64->24) via warp mma.sync fp16 single-pass.
// Chunk = 72 cols = 8 whole inputs. A K-major (pitch 2*ROWS+16), B pitch 176B.
// R17: ROWS is a template param; layer2 uses 64-row CTAs (7 CTAs/SM, 1.98
// waves at 97.7% fill) to fix wave imbalance + occupancy.
// ---------------------------------------------------------------------------

#define MAXN (32 * 64 * 64)

__device__ float g_h1[64 * MAXN];
__device__ float g_h2[64 * MAXN];
__device__ __align__(16) __half g_W0[64 * 144];
__device__ __align__(16) __half g_W1[64 * 576];
__device__ __align__(16) __half g_W2[24 * 576];

// ------------------------------- helpers -----------------------------------

__device__ __forceinline__ uint32_t smem_u32(const void* p) {
    uint32_t a;
    asm("{ .reg .u64 t; cvta.to.shared.u64 t, %1; cvt.u32.u64 %0, t; }"
        : "=r"(a) : "l"(p));
    return a;
}
__device__ __forceinline__ void ldsm4(uint32_t addr, uint32_t r[4]) {
    asm volatile("ldmatrix.sync.aligned.m8n8.x4.shared.b16 {%0,%1,%2,%3}, [%4];"
                 : "=r"(r[0]), "=r"(r[1]), "=r"(r[2]), "=r"(r[3]) : "r"(addr));
}
__device__ __forceinline__ void ldsm4t(uint32_t addr, uint32_t r[4]) {
    asm volatile("ldmatrix.sync.aligned.m8n8.x4.trans.shared.b16 {%0,%1,%2,%3}, [%4];"
                 : "=r"(r[0]), "=r"(r[1]), "=r"(r[2]), "=r"(r[3]) : "r"(addr));
}
__device__ __forceinline__ void ldsm2(uint32_t addr, uint32_t r[2]) {
    asm volatile("ldmatrix.sync.aligned.m8n8.x2.shared.b16 {%0,%1}, [%2];"
                 : "=r"(r[0]), "=r"(r[1]) : "r"(addr));
}
__device__ __forceinline__ void mma16816(float c[4], const uint32_t a[4],
                                         uint32_t b0, uint32_t b1) {
    asm volatile(
        "mma.sync.aligned.m16n8k16.row.col.f32.f16.f16.f32 "
        "{%0,%1,%2,%3},{%4,%5,%6,%7},{%8,%9},{%0,%1,%2,%3};"
        : "+f"(c[0]), "+f"(c[1]), "+f"(c[2]), "+f"(c[3])
        : "r"(a[0]), "r"(a[1]), "r"(a[2]), "r"(a[3]), "r"(b0), "r"(b1));
}
__device__ __forceinline__ void sts64(uint32_t addr, uint32_t v0, uint32_t v1) {
    asm volatile("st.shared.v2.b32 [%0], {%1,%2};" :: "r"(addr), "r"(v0), "r"(v1));
}
__device__ __forceinline__ void sts128z(uint32_t addr) {
    asm volatile("st.shared.v4.b32 [%0], {%1,%1,%1,%1};" :: "r"(addr), "r"(0u));
}
__device__ __forceinline__ void cp16(uint32_t dst, const void* src) {
    asm volatile("cp.async.ca.shared.global [%0], [%1], 16;"
                 :: "r"(dst), "l"(src) : "memory");
}
__device__ __forceinline__ void cp_commit() {
    asm volatile("cp.async.commit_group;" ::: "memory");
}
__device__ __forceinline__ void cp_wait0() {
    asm volatile("cp.async.wait_group 0;" ::: "memory");
}
__device__ __forceinline__ uint32_t h2u(__half2 h) {
    return *reinterpret_cast<uint32_t*>(&h);
}

// ------------------------------- fold kernel (fused, all 3 layers) ---------
__global__ void fold_all(const float* c0, const float* b0, const float* s0,
                         const float* c1, const float* b1, const float* s1,
                         const float* c2, const float* b2, const float* s2,
                         __half* W0, __half* W1, __half* W2) {
    int idx = blockIdx.x * blockDim.x + threadIdx.x;
    const float *coef, *sbp, *ss;
    __half* W;
    int IN, OUT, KPAD;
    if (idx < 64 * 144) {
        coef = c0; sbp = b0; ss = s0; W = W0;
        IN = 12; OUT = 64; KPAD = 144;
    } else if (idx < 64 * 144 + 64 * 576) {
        idx -= 64 * 144;
        coef = c1; sbp = b1; ss = s1; W = W1;
        IN = 64; OUT = 64; KPAD = 576;
    } else if (idx < 64 * 144 + 64 * 576 + 24 * 576) {
        idx -= 64 * 144 + 64 * 576;
        coef = c2; sbp = b2; ss = s2; W = W2;
        IN = 64; OUT = 24; KPAD = 576;
    } else return;
    int o = idx / KPAD, k = idx % KPAD;
    float w = 0.0f;
    if (k < IN * 9) {
        int i = k / 9, j = k % 9;
        w = (j == 0) ? sbp[i * OUT + o] : coef[(i * OUT + o) * 8 + (j - 1)] * ss[i * OUT + o];
    }
    W[idx] = __float2half_rn(w);
}

// ------------------------------- layer kernel ------------------------------
template <int ROWS, int IN, int OUT, int K, int KPAD, int NCHUNK,
          bool IN_NCHW, bool OUT_NCHW, int CSPLIT, int MINB>
__global__ void __launch_bounds__(ROWS * 2, MINB)
kan_mma(const float* __restrict__ hin, const float* __restrict__ grid,
        const __half* __restrict__ W, float* __restrict__ hout, int N) {
    constexpr int NTHREADS = ROWS * 2;
    constexpr int MT = CSPLIT;
    constexpr int NTL = OUT / 8 / CSPLIT;
    constexpr int NTL2 = NTL / 2;
    constexpr int OUTL = OUT / CSPLIT;
    constexpr int APITCH = ROWS * 2 + 16;
    constexpr int ABUF = 80 * APITCH;
    constexpr int BPITCH = 176;
    constexpr int BBUF = OUT * BPITCH;
    constexpr int SMTOT = 2 * ABUF + 2 * BBUF;
    constexpr bool KFULL = (K % 72 == 0);
    constexpr int NQ = ROWS / 4;  // quads

    extern __shared__ char dsm[];
    const uint32_t sb = smem_u32(dsm);
    const uint32_t BBASE = sb + 2 * ABUF;

    const int tid = threadIdx.x;
    const int wid = tid >> 5;
    const int lane = tid & 31;
    const int row0 = blockIdx.x * ROWS;

    const float t0 = __ldg(grid + 0);
    const float invh = 1.0f / (__ldg(grid + 1) - t0);
    const float t11 = __ldg(grid + 11);

    // scatter mapping: thread owns row quad, one input per chunk
    const int q = tid & (NQ - 1);
    const int il = tid / NQ;  // 0..7
    const int img = row0 >> 12;
    const int pix0 = (row0 & 4095) + 4 * q;

    // warp tiling
    const int rg = wid / CSPLIT;
    const int cg = wid % CSPLIT;
    const int ob = cg * OUTL;

    // fragment addressing
    const int gq = tid >> 3 & 3;  // lane>>3
    const int gql = lane >> 3;
    const int a_k = (lane & 7) + ((gql >> 1) * 8);
    uint32_t a_sw[MT];
#pragma unroll
    for (int mt = 0; mt < MT; mt++) {
        int a_m = rg * (16 * CSPLIT) + mt * 16 + (gql & 1) * 8;
        a_sw[mt] = (uint32_t)(a_k * APITCH + a_m * 2);
    }
    const int brow = (lane & 7) + 8 * (gql >> 1);
    const int bseg = gql & 1;
    (void)gq;

    float acc[MT][NTL][4];
#pragma unroll
    for (int mt = 0; mt < MT; mt++)
#pragma unroll
        for (int p = 0; p < NTL; p++)
#pragma unroll
            for (int qq = 0; qq < 4; qq++) acc[mt][p][qq] = 0.0f;

    // ---------------- prologue: zero ALL smem ----------------
    for (int z = tid * 16; z < SMTOT; z += NTHREADS * 16) sts128z(sb + z);

    // ---------------- pipeline helpers ----------------
    auto prefetch = [&](int c, float4& xr) {
        int i = c * 8 + il;
        if (i < IN) {
            const float* src;
            if (IN_NCHW) src = hin + (img * IN + i) * 4096 + pix0;
            else src = hin + i * N + row0 + 4 * q;
            xr = *reinterpret_cast<const float4*>(src);
        } else {
            xr = make_float4(0.f, 0.f, 0.f, 0.f);
        }
    };

    auto stageB = [&](int c, int st) {
        uint32_t bb = BBASE + (uint32_t)st * BBUF;
        for (int v = tid; v < OUT * 9; v += NTHREADS) {
            int o = v / 9, seg = v - o * 9;
            const __half* src = W + o * KPAD + c * 72 + seg * 8;
            cp16(bb + (uint32_t)(o * BPITCH + seg * 16), src);
        }
        cp_commit();
    };

    auto scatter = [&](int c, int st, const float4& xr) {
        int i = c * 8 + il;
        if (IN < 64 && i >= IN) return;  // layer0 tail only
        const uint32_t abase = sb + (uint32_t)st * ABUF + (uint32_t)(q * 8) +
                               (uint32_t)((9 * il) * APITCH);
        float xv[4] = {xr.x, xr.y, xr.z, xr.w};
        uint32_t O[4][4];
        float f0[4];
#pragma unroll
        for (int rr = 0; rr < 4; rr++) {
            float x = xv[rr];
            f0[rr] = __fdividef(x, 1.0f + __expf(-x));  // silu

            bool inr = (x >= t0) && (x < t11);
            float s = (x - t0) * invh;
            s = fminf(fmaxf(s, 0.0f), 10.999f);
            int m = (int)s;
            float u1 = s - (float)m;
            float um = 1.0f - u1;
            float u2 = u1 * u1, u3 = u2 * u1;
            float fl = inr ? (1.0f / 6.0f) : 0.0f;
            float v0 = um * um * um * fl;
            float v1 = (3.0f * u3 - 6.0f * u2 + 4.0f) * fl;
            float v2 = (-3.0f * u3 + 3.0f * u2 + 3.0f * u1 + 1.0f) * fl;
            float v3 = u3 * fl;

            float w0 = (m >= 3) ? v0 : 0.0f;
            float w1 = (m >= 2 && m <= 9) ? v1 : 0.0f;
            float w2 = (m >= 1 && m <= 8) ? v2 : 0.0f;
            float w3 = (m <= 7) ? v3 : 0.0f;
            uint32_t P0 = h2u(__floats2half2_rn(w0, w1));
            uint32_t P1 = h2u(__floats2half2_rn(w2, w3));

            int rho = (3 - m) & 7;
            int q1 = (rho >> 1) & 1, q2 = (rho >> 1) & 2, od = rho & 1;
            uint32_t A0 = q1 ? P1 : P0;
            uint32_t A1 = q1 ? 0u : P1;
            uint32_t A3 = q1 ? P0 : 0u;
            uint32_t B0 = q2 ? 0u : A0;
            uint32_t B1 = q2 ? A3 : A1;
            uint32_t B2 = q2 ? A0 : 0u;
            uint32_t B3 = q2 ? A1 : A3;
            uint32_t C0 = od ? __byte_perm(B0, B1, 0x5432) : B0;
            uint32_t C1 = od ? __byte_perm(B1, B2, 0x5432) : B1;
            uint32_t C2 = od ? __byte_perm(B2, B3, 0x5432) : B2;
            uint32_t C3 = od ? __byte_perm(B3, B0, 0x5432) : B3;
            O[rr][0] = C0; O[rr][1] = C1; O[rr][2] = C2; O[rr][3] = C3;
        }

        sts64(abase, h2u(__floats2half2_rn(f0[0], f0[1])),
              h2u(__floats2half2_rn(f0[2], f0[3])));
#pragma unroll
        for (int j2 = 0; j2 < 4; j2++) {
            uint32_t lo01 = __byte_perm(O[0][j2], O[1][j2], 0x5410);
            uint32_t lo23 = __byte_perm(O[2][j2], O[3][j2], 0x5410);
            uint32_t hi01 = __byte_perm(O[0][j2], O[1][j2], 0x7632);
            uint32_t hi23 = __byte_perm(O[2][j2], O[3][j2], 0x7632);
            sts64(abase + (uint32_t)((1 + 2 * j2) * APITCH), lo01, lo23);
            sts64(abase + (uint32_t)((2 + 2 * j2) * APITCH), hi01, hi23);
        }
    };

    auto mma_chunk = [&](int c, int st) {
        const uint32_t A0a = sb + (uint32_t)st * ABUF;
        const uint32_t Bh = BBASE + (uint32_t)st * BBUF;
        const int ksn = KFULL ? 5 : ((K - c * 72 + 15) >> 4 < 5 ? (K - c * 72 + 15) >> 4 : 5);
#pragma unroll
        for (int ks = 0; ks < 5; ks++) {
            if (!KFULL && ks >= ksn) break;
            uint32_t a[MT][4];
#pragma unroll
            for (int mt = 0; mt < MT; mt++)
                ldsm4t(A0a + a_sw[mt] + (uint32_t)(ks * 16 * APITCH), a[mt]);
#pragma unroll
            for (int qq = 0; qq < NTL2; qq++) {
                uint32_t bo = (uint32_t)((ob + 16 * qq + brow) * BPITCH + bseg * 16 + ks * 32);
                uint32_t bh[4];
                ldsm4(Bh + bo, bh);
#pragma unroll
                for (int mt = 0; mt < MT; mt++) {
                    mma16816(acc[mt][2 * qq], a[mt], bh[0], bh[1]);
                    mma16816(acc[mt][2 * qq + 1], a[mt], bh[2], bh[3]);
                }
            }
            if constexpr (NTL & 1) {
                uint32_t bo = (uint32_t)((ob + 8 * (NTL - 1) + (lane & 7)) * BPITCH +
                                         ((lane >> 3) & 1) * 16 + ks * 32);
                uint32_t bh2[2];
                ldsm2(Bh + bo, bh2);
#pragma unroll
                for (int mt = 0; mt < MT; mt++)
                    mma16816(acc[mt][NTL - 1], a[mt], bh2[0], bh2[1]);
            }
        }
    };

    // ---------------- main pipeline ----------------
    float4 xb0, xb1;
    prefetch(0, xb0);
    if (NCHUNK > 1) prefetch(1, xb1);
    __syncthreads();  // prologue zero visible before scatter
    stageB(0, 0);
    scatter(0, 0, xb0);
    cp_wait0();
    __syncthreads();

    for (int c = 0; c < NCHUNK; c++) {
        const int st = c & 1;
        if (c + 2 < NCHUNK) prefetch(c + 2, (c & 1) ? xb1 : xb0);
        if (c + 1 < NCHUNK) stageB(c + 1, st ^ 1);
        mma_chunk(c, st);
        if (c + 1 < NCHUNK) scatter(c + 1, st ^ 1, ((c + 1) & 1) ? xb1 : xb0);
        cp_wait0();
        __syncthreads();
    }

    // ---------------- epilogue: smem transpose -> coalesced STG ----------------
    constexpr int SP = ROWS + 4;
    float* S = reinterpret_cast<float*>(dsm);  // reuse A region
    __syncthreads();
    {
#pragma unroll
        for (int mt = 0; mt < MT; mt++) {
            const int er0 = rg * (16 * CSPLIT) + mt * 16 + (lane >> 2);
            const int er1 = er0 + 8;
#pragma unroll
            for (int p = 0; p < NTL; p++) {
                int o = ob + p * 8 + (lane & 3) * 2;
                S[o * SP + er0] = acc[mt][p][0];
                S[(o + 1) * SP + er0] = acc[mt][p][1];
                S[o * SP + er1] = acc[mt][p][2];
                S[(o + 1) * SP + er1] = acc[mt][p][3];
            }
        }
    }
    __syncthreads();
    for (int idx = tid; idx < OUT * ROWS; idx += NTHREADS) {
        int o = idx / ROWS;
        int rr = idx - o * ROWS;
        float val = S[o * SP + rr];
        if (OUT_NCHW) hout[(img * OUT + o) * 4096 + (row0 & 4095) + rr] = val;
        else hout[o * N + row0 + rr] = val;
    }
}

// ------------------------------- launch ------------------------------------

extern "C" void kernel_launch(void* const* d_in, const int* in_sizes, int n_in,
                              void* d_out, int out_size) {
    const float* x     = (const float*)d_in[0];
    const float* grid0 = (const float*)d_in[1];
    const float* coef0 = (const float*)d_in[2];
    const float* sb0   = (const float*)d_in[3];
    const float* ss0   = (const float*)d_in[4];
    const float* grid1 = (const float*)d_in[5];
    const float* coef1 = (const float*)d_in[6];
    const float* sb1   = (const float*)d_in[7];
    const float* ss1   = (const float*)d_in[8];
    const float* grid2 = (const float*)d_in[9];
    const float* coef2 = (const float*)d_in[10];
    const float* sb2   = (const float*)d_in[11];
    const float* ss2   = (const float*)d_in[12];
    float* out = (float*)d_out;

    int N = in_sizes[0] / 12;
    if (N > MAXN) N = MAXN;

    float *h1, *h2;
    __half *W0, *W1, *W2;
    cudaGetSymbolAddress((void**)&h1, g_h1);
    cudaGetSymbolAddress((void**)&h2, g_h2);
    cudaGetSymbolAddress((void**)&W0, g_W0);
    cudaGetSymbolAddress((void**)&W1, g_W1);
    cudaGetSymbolAddress((void**)&W2, g_W2);

    constexpr int FOLD_TOTAL = 64 * 144 + 64 * 576 + 24 * 576;
    fold_all<<<(FOLD_TOTAL + 255) / 256, 256>>>(coef0, sb0, ss0, coef1, sb1, ss1,
                                                coef2, sb2, ss2, W0, W1, W2);

    auto k0 = kan_mma<128, 12, 64, 108, 144, 2, true, false, 2, 3>;
    auto k1 = kan_mma<128, 64, 64, 576, 576, 8, false, false, 2, 3>;
    auto k2 = kan_mma<64, 64, 24, 576, 576, 8, false, true, 1, 7>;

    constexpr int SM01 = 2 * 80 * 272 + 2 * 64 * 176;  // 66048
    constexpr int SM2  = 2 * 80 * 144 + 2 * 24 * 176;  // 31488
    cudaFuncSetAttribute(k0, cudaFuncAttributeMaxDynamicSharedMemorySize, SM01);
    cudaFuncSetAttribute(k1, cudaFuncAttributeMaxDynamicSharedMemorySize, SM01);
    cudaFuncSetAttribute(k2, cudaFuncAttributeMaxDynamicSharedMemorySize, SM2);

    k0<<<N / 128, 256, SM01>>>(x, grid0, W0, h1, N);
    k1<<<N / 128, 256, SM01>>>(h1, grid1, W1, h2, N);
    k2<<<N / 64, 128, SM2>>>(h2, grid2, W2, out, N);
}